// round 3
// baseline (speedup 1.0000x reference)
#include <cuda_runtime.h>
#include <cuda_fp16.h>
#include <math.h>

#define NMAX 100000
#define EMAX 1600000
#define DEMB 64
#define SCAN_B 1024

// Scratch (static device globals — no allocation)
__device__ float   g_h[NMAX * DEMB];       // node features (fp32)
__device__ __half2 g_hwh[NMAX * 32];       // transformed features h @ W (fp16, 64 per node)
__device__ float   g_deg[NMAX];            // degree -> dis
__device__ float   g_selfnorm[NMAX];       // dis^2
__device__ int     g_cnt[NMAX];            // in-degree histogram
__device__ int     g_off[NMAX + 1];        // CSR offsets (by target)
__device__ int     g_woff[NMAX];           // write cursors for bucket fill
__device__ int     g_bsum[(NMAX + SCAN_B - 1) / SCAN_B + 1];
__device__ int2    g_csr[EMAX];            // {src, float_bits(norm)} sorted by target

// ---------------- degree histogram ----------------

__global__ void k_init(int n) {
    int i = blockIdx.x * blockDim.x + threadIdx.x;
    if (i < n) { g_deg[i] = 1.0f; g_cnt[i] = 0; }  // self-loop weight = 1
}

__global__ void k_hist(const int* __restrict__ ei,
                       const float* __restrict__ ew, int e) {
    int i = blockIdx.x * blockDim.x + threadIdx.x;
    if (i < e) {
        int c = ei[e + i];                 // col = target
        atomicAdd(&g_deg[c], ew[i]);
        atomicAdd(&g_cnt[c], 1);
    }
}

__global__ void k_dis(int n) {
    int i = blockIdx.x * blockDim.x + threadIdx.x;
    if (i < n) {
        float d = g_deg[i];
        float r = (d > 0.0f) ? rsqrtf(d) : 0.0f;
        g_deg[i] = r;                      // reuse as dis
        g_selfnorm[i] = r * r;
    }
}

// ---------------- exclusive scan of g_cnt -> g_off ----------------

__global__ void k_scan1(int n) {
    __shared__ int s[SCAN_B];
    int gid = blockIdx.x * SCAN_B + threadIdx.x;
    int v = (gid < n) ? g_cnt[gid] : 0;
    s[threadIdx.x] = v;
    __syncthreads();
#pragma unroll
    for (int off = 1; off < SCAN_B; off <<= 1) {
        int t = (threadIdx.x >= off) ? s[threadIdx.x - off] : 0;
        __syncthreads();
        s[threadIdx.x] += t;
        __syncthreads();
    }
    if (gid < n) g_off[gid] = s[threadIdx.x] - v;  // exclusive
    if (threadIdx.x == SCAN_B - 1) g_bsum[blockIdx.x] = s[SCAN_B - 1];
}

__global__ void k_scan2(int nb, int n, int e) {
    if (threadIdx.x == 0 && blockIdx.x == 0) {
        int run = 0;
        for (int i = 0; i < nb; i++) {
            int t = g_bsum[i];
            g_bsum[i] = run;
            run += t;
        }
        g_off[n] = e;
    }
}

__global__ void k_scan3(int n) {
    int gid = blockIdx.x * SCAN_B + threadIdx.x;
    if (gid < n) {
        int o = g_off[gid] + g_bsum[blockIdx.x];
        g_off[gid] = o;
        g_woff[gid] = o;
    }
}

// ---------------- bucket fill: edges sorted by target + norm ----------------

__global__ void k_build(const int* __restrict__ ei,
                        const float* __restrict__ ew, int e) {
    int i = blockIdx.x * blockDim.x + threadIdx.x;
    if (i < e) {
        int r = ei[i];
        int c = ei[e + i];
        float nm = g_deg[r] * ew[i] * g_deg[c];  // dis[row]*ew*dis[col]
        int pos = atomicAdd(&g_woff[c], 1);
        g_csr[pos] = make_int2(r, __float_as_int(nm));
    }
}

// ---------------- encoder MLP: h = relu(x@W1+b1)@W2+b2 ----------------

__global__ void k_encoder(const float* __restrict__ x,
                          const float* __restrict__ w1,
                          const float* __restrict__ b1,
                          const float* __restrict__ w2,
                          const float* __restrict__ b2, int n) {
    __shared__ float4 W2s[DEMB * 16];
    __shared__ float  W1s[2 * DEMB];
    __shared__ float  B1s[DEMB];
    __shared__ float4 B2s[16];
    for (int i = threadIdx.x; i < DEMB * 16; i += blockDim.x)
        W2s[i] = reinterpret_cast<const float4*>(w2)[i];
    for (int i = threadIdx.x; i < 2 * DEMB; i += blockDim.x) W1s[i] = w1[i];
    for (int i = threadIdx.x; i < DEMB; i += blockDim.x) B1s[i] = b1[i];
    for (int i = threadIdx.x; i < 16; i += blockDim.x)
        B2s[i] = reinterpret_cast<const float4*>(b2)[i];
    __syncthreads();

    int nd = blockIdx.x * blockDim.x + threadIdx.x;
    if (nd >= n) return;
    float x0 = x[nd * 2 + 0], x1 = x[nd * 2 + 1];

    float h1[DEMB];
#pragma unroll
    for (int j = 0; j < DEMB; j++)
        h1[j] = fmaxf(fmaf(x0, W1s[j], fmaf(x1, W1s[DEMB + j], B1s[j])), 0.0f);

    float4* out = reinterpret_cast<float4*>(g_h + nd * DEMB);
#pragma unroll
    for (int j4 = 0; j4 < 16; j4++) {
        float4 a = B2s[j4];
#pragma unroll
        for (int k = 0; k < DEMB; k++) {
            float4 w = W2s[k * 16 + j4];
            a.x = fmaf(h1[k], w.x, a.x);
            a.y = fmaf(h1[k], w.y, a.y);
            a.z = fmaf(h1[k], w.z, a.z);
            a.w = fmaf(h1[k], w.w, a.w);
        }
        out[j4] = a;
    }
}

// ---------------- GCN transform: hw(fp16) = h@W[l]; g_h = selfnorm*hw (in place) ----------------

__global__ void k_gemm_gcn(const float* __restrict__ gcn_w, int l, int n) {
    __shared__ float4 Ws[DEMB * 16];
    const float4* Wg = reinterpret_cast<const float4*>(gcn_w + (size_t)l * DEMB * DEMB);
    for (int i = threadIdx.x; i < DEMB * 16; i += blockDim.x) Ws[i] = Wg[i];
    __syncthreads();

    int nd = blockIdx.x * blockDim.x + threadIdx.x;
    if (nd >= n) return;

    float h[DEMB];
    const float4* hv = reinterpret_cast<const float4*>(g_h + nd * DEMB);
#pragma unroll
    for (int i = 0; i < 16; i++) {
        float4 t = hv[i];
        h[i * 4 + 0] = t.x; h[i * 4 + 1] = t.y;
        h[i * 4 + 2] = t.z; h[i * 4 + 3] = t.w;
    }
    float sn = g_selfnorm[nd];
    __half2* hwv = g_hwh + (size_t)nd * 32;
    float4* selfv = reinterpret_cast<float4*>(g_h + nd * DEMB);

#pragma unroll
    for (int j4 = 0; j4 < 16; j4++) {
        float4 a = make_float4(0.f, 0.f, 0.f, 0.f);
#pragma unroll
        for (int k = 0; k < DEMB; k++) {
            float4 w = Ws[k * 16 + j4];
            a.x = fmaf(h[k], w.x, a.x);
            a.y = fmaf(h[k], w.y, a.y);
            a.z = fmaf(h[k], w.z, a.z);
            a.w = fmaf(h[k], w.w, a.w);
        }
        hwv[j4 * 2 + 0] = __floats2half2_rn(a.x, a.y);
        hwv[j4 * 2 + 1] = __floats2half2_rn(a.z, a.w);
        selfv[j4] = make_float4(a.x * sn, a.y * sn, a.z * sn, a.w * sn);
    }
}

// ---------------- pull aggregation: h = relu(self + Σ norm*hw16[src] + b) ----------------
// 16 threads per node; lane owns 4 features. fp16 gather = exactly one 128B line/node.

__global__ void k_aggregate(const float* __restrict__ gcn_b, int l, int n) {
    int idx = blockIdx.x * blockDim.x + threadIdx.x;
    int v = idx >> 4;
    if (v >= n) return;
    int lane = idx & 15;

    int j   = g_off[v];
    int end = g_off[v + 1];

    // start from exact fp32 self contribution (written by GEMM) + bias
    float4 acc = reinterpret_cast<const float4*>(g_h)[(size_t)v * 16 + lane];
    float4 b = __ldg(reinterpret_cast<const float4*>(gcn_b + (size_t)l * DEMB) + lane);
    acc.x += b.x; acc.y += b.y; acc.z += b.z; acc.w += b.w;

    const __half2* hw = g_hwh;

    // unroll by 2 for independent address chains
    for (; j + 1 < end; j += 2) {
        int2 p0 = __ldg(&g_csr[j]);
        int2 p1 = __ldg(&g_csr[j + 1]);
        float n0 = __int_as_float(p0.y);
        float n1 = __int_as_float(p1.y);
        uint2 r0 = *reinterpret_cast<const uint2*>(hw + (size_t)p0.x * 32 + lane * 2);
        uint2 r1 = *reinterpret_cast<const uint2*>(hw + (size_t)p1.x * 32 + lane * 2);
        float2 a0 = __half22float2(*reinterpret_cast<__half2*>(&r0.x));
        float2 b0 = __half22float2(*reinterpret_cast<__half2*>(&r0.y));
        float2 a1 = __half22float2(*reinterpret_cast<__half2*>(&r1.x));
        float2 b1h = __half22float2(*reinterpret_cast<__half2*>(&r1.y));
        acc.x = fmaf(a0.x, n0, acc.x); acc.y = fmaf(a0.y, n0, acc.y);
        acc.z = fmaf(b0.x, n0, acc.z); acc.w = fmaf(b0.y, n0, acc.w);
        acc.x = fmaf(a1.x, n1, acc.x); acc.y = fmaf(a1.y, n1, acc.y);
        acc.z = fmaf(b1h.x, n1, acc.z); acc.w = fmaf(b1h.y, n1, acc.w);
    }
    if (j < end) {
        int2 p = __ldg(&g_csr[j]);
        float nm = __int_as_float(p.y);
        uint2 r = *reinterpret_cast<const uint2*>(hw + (size_t)p.x * 32 + lane * 2);
        float2 a0 = __half22float2(*reinterpret_cast<__half2*>(&r.x));
        float2 b0 = __half22float2(*reinterpret_cast<__half2*>(&r.y));
        acc.x = fmaf(a0.x, nm, acc.x); acc.y = fmaf(a0.y, nm, acc.y);
        acc.z = fmaf(b0.x, nm, acc.z); acc.w = fmaf(b0.y, nm, acc.w);
    }

    acc.x = fmaxf(acc.x, 0.0f);
    acc.y = fmaxf(acc.y, 0.0f);
    acc.z = fmaxf(acc.z, 0.0f);
    acc.w = fmaxf(acc.w, 0.0f);
    reinterpret_cast<float4*>(g_h)[(size_t)v * 16 + lane] = acc;
}

// ---------------- decoder + softmax + residual ----------------

__global__ void k_decoder(const float* __restrict__ x,
                          const float* __restrict__ w1,
                          const float* __restrict__ b1,
                          const float* __restrict__ w2,
                          const float* __restrict__ b2,
                          float* __restrict__ out, int n) {
    __shared__ float4 W1s[DEMB * 16];
    __shared__ float4 B1s[16];
    __shared__ float  W2s[DEMB * 2];
    __shared__ float  B2s[2];
    for (int i = threadIdx.x; i < DEMB * 16; i += blockDim.x)
        W1s[i] = reinterpret_cast<const float4*>(w1)[i];
    for (int i = threadIdx.x; i < 16; i += blockDim.x)
        B1s[i] = reinterpret_cast<const float4*>(b1)[i];
    for (int i = threadIdx.x; i < DEMB * 2; i += blockDim.x) W2s[i] = w2[i];
    for (int i = threadIdx.x; i < 2; i += blockDim.x) B2s[i] = b2[i];
    __syncthreads();

    int nd = blockIdx.x * blockDim.x + threadIdx.x;
    if (nd >= n) return;

    float h[DEMB];
    const float4* hv = reinterpret_cast<const float4*>(g_h + nd * DEMB);
#pragma unroll
    for (int i = 0; i < 16; i++) {
        float4 t = hv[i];
        h[i * 4 + 0] = t.x; h[i * 4 + 1] = t.y;
        h[i * 4 + 2] = t.z; h[i * 4 + 3] = t.w;
    }

    float o0 = B2s[0], o1 = B2s[1];
#pragma unroll
    for (int j4 = 0; j4 < 16; j4++) {
        float4 a = B1s[j4];
#pragma unroll
        for (int k = 0; k < DEMB; k++) {
            float4 w = W1s[k * 16 + j4];
            a.x = fmaf(h[k], w.x, a.x);
            a.y = fmaf(h[k], w.y, a.y);
            a.z = fmaf(h[k], w.z, a.z);
            a.w = fmaf(h[k], w.w, a.w);
        }
        a.x = fmaxf(a.x, 0.f); a.y = fmaxf(a.y, 0.f);
        a.z = fmaxf(a.z, 0.f); a.w = fmaxf(a.w, 0.f);
        int j = j4 * 4;
        o0 += a.x * W2s[(j + 0) * 2 + 0] + a.y * W2s[(j + 1) * 2 + 0]
            + a.z * W2s[(j + 2) * 2 + 0] + a.w * W2s[(j + 3) * 2 + 0];
        o1 += a.x * W2s[(j + 0) * 2 + 1] + a.y * W2s[(j + 1) * 2 + 1]
            + a.z * W2s[(j + 2) * 2 + 1] + a.w * W2s[(j + 3) * 2 + 1];
    }

    float mx = fmaxf(o0, o1);
    float e0 = __expf(o0 - mx), e1 = __expf(o1 - mx);
    float inv = 1.0f / (e0 + e1);
    out[nd * 2 + 0] = e0 * inv + 2.0f * x[nd * 2 + 0];
    out[nd * 2 + 1] = e1 * inv;
}

// ---------------- launch ----------------

extern "C" void kernel_launch(void* const* d_in, const int* in_sizes, int n_in,
                              void* d_out, int out_size) {
    const float* x      = (const float*)d_in[0];
    const int*   ei     = (const int*)d_in[1];
    const float* ew     = (const float*)d_in[2];
    const float* enc_w1 = (const float*)d_in[3];
    const float* enc_b1 = (const float*)d_in[4];
    const float* enc_w2 = (const float*)d_in[5];
    const float* enc_b2 = (const float*)d_in[6];
    const float* gcn_w  = (const float*)d_in[7];
    const float* gcn_b  = (const float*)d_in[8];
    const float* dec_w1 = (const float*)d_in[9];
    const float* dec_b1 = (const float*)d_in[10];
    const float* dec_w2 = (const float*)d_in[11];
    const float* dec_b2 = (const float*)d_in[12];
    float* out = (float*)d_out;

    int n = in_sizes[0] / 2;
    int e = in_sizes[1] / 2;
    int L = in_sizes[7] / (DEMB * DEMB);

    const int BT = 256;
    int nb_n  = (n + BT - 1) / BT;
    int nb_e  = (e + BT - 1) / BT;
    int nb_ag = (n * 16 + BT - 1) / BT;
    int nb_sc = (n + SCAN_B - 1) / SCAN_B;

    // CSR build (once per launch)
    k_init<<<nb_n, BT>>>(n);
    k_hist<<<nb_e, BT>>>(ei, ew, e);
    k_dis<<<nb_n, BT>>>(n);
    k_scan1<<<nb_sc, SCAN_B>>>(n);
    k_scan2<<<1, 32>>>(nb_sc, n, e);
    k_scan3<<<nb_sc, SCAN_B>>>(n);
    k_build<<<nb_e, BT>>>(ei, ew, e);

    // encoder
    k_encoder<<<nb_n, BT>>>(x, enc_w1, enc_b1, enc_w2, enc_b2, n);

    // GCN layers: transform then pull-aggregate (bias+relu fused)
    for (int l = 0; l < L; l++) {
        k_gemm_gcn<<<nb_n, BT>>>(gcn_w, l, n);
        k_aggregate<<<nb_ag, BT>>>(gcn_b, l, n);
    }

    // decoder
    k_decoder<<<nb_n, BT>>>(x, dec_w1, dec_b1, dec_w2, dec_b2, out, n);
}

// round 4
// speedup vs baseline: 1.0438x; 1.0438x over previous
#include <cuda_runtime.h>
#include <cuda_fp16.h>
#include <math.h>

#define NMAX 100000
#define EMAX 1600000
#define DEMB 64
#define SCAN_B 1024

// Scratch (static device globals — no allocation)
__device__ float   g_h[NMAX * DEMB];       // node features (fp32)
__device__ __half2 g_hwh[NMAX * 32];       // transformed features h @ W (fp16)
__device__ float   g_deg[NMAX];            // degree -> dis
__device__ float   g_selfnorm[NMAX];       // dis^2
__device__ int     g_cnt[NMAX];            // in-degree histogram
__device__ int     g_off[NMAX + 1];        // CSR offsets (by target)
__device__ int     g_woff[NMAX];           // write cursors for bucket fill
__device__ int     g_bsum[(NMAX + SCAN_B - 1) / SCAN_B + 1];
__device__ int2    g_csr[EMAX];            // {src, float_bits(norm)} sorted by target

// ---------------- packed f32x2 helpers ----------------

__device__ __forceinline__ unsigned long long pk(float v) {
    unsigned long long r;
    asm("mov.b64 %0, {%1, %1};" : "=l"(r) : "f"(v));
    return r;
}
__device__ __forceinline__ void fma2(unsigned long long& d,
                                     unsigned long long a,
                                     unsigned long long b) {
    asm("fma.rn.f32x2 %0, %1, %2, %0;" : "+l"(d) : "l"(a), "l"(b));
}
__device__ __forceinline__ float2 upk(unsigned long long v) {
    float2 f;
    asm("mov.b64 {%0, %1}, %2;" : "=f"(f.x), "=f"(f.y) : "l"(v));
    return f;
}

// ---------------- degree histogram ----------------

__global__ void k_init(int n) {
    int i = blockIdx.x * blockDim.x + threadIdx.x;
    if (i < n) { g_deg[i] = 1.0f; g_cnt[i] = 0; }  // self-loop weight = 1
}

__global__ void k_hist(const int* __restrict__ ei,
                       const float* __restrict__ ew, int e) {
    int i = blockIdx.x * blockDim.x + threadIdx.x;
    if (i < e) {
        int c = ei[e + i];                 // col = target
        atomicAdd(&g_deg[c], ew[i]);
        atomicAdd(&g_cnt[c], 1);
    }
}

__global__ void k_dis(int n) {
    int i = blockIdx.x * blockDim.x + threadIdx.x;
    if (i < n) {
        float d = g_deg[i];
        float r = (d > 0.0f) ? rsqrtf(d) : 0.0f;
        g_deg[i] = r;                      // reuse as dis
        g_selfnorm[i] = r * r;
    }
}

// ---------------- exclusive scan of g_cnt -> g_off ----------------

__global__ void k_scan1(int n) {
    __shared__ int s[SCAN_B];
    int gid = blockIdx.x * SCAN_B + threadIdx.x;
    int v = (gid < n) ? g_cnt[gid] : 0;
    s[threadIdx.x] = v;
    __syncthreads();
#pragma unroll
    for (int off = 1; off < SCAN_B; off <<= 1) {
        int t = (threadIdx.x >= off) ? s[threadIdx.x - off] : 0;
        __syncthreads();
        s[threadIdx.x] += t;
        __syncthreads();
    }
    if (gid < n) g_off[gid] = s[threadIdx.x] - v;  // exclusive
    if (threadIdx.x == SCAN_B - 1) g_bsum[blockIdx.x] = s[SCAN_B - 1];
}

// parallel exclusive scan of block sums (nb <= 128) — one block, shared scan
__global__ void k_scan2(int nb, int n, int e) {
    __shared__ int s[128];
    int t = threadIdx.x;
    int v = (t < nb) ? g_bsum[t] : 0;
    s[t] = v;
    __syncthreads();
#pragma unroll
    for (int off = 1; off < 128; off <<= 1) {
        int u = (t >= off) ? s[t - off] : 0;
        __syncthreads();
        s[t] += u;
        __syncthreads();
    }
    if (t < nb) g_bsum[t] = s[t] - v;  // exclusive
    if (t == 0) g_off[n] = e;
}

__global__ void k_scan3(int n) {
    int gid = blockIdx.x * SCAN_B + threadIdx.x;
    if (gid < n) {
        int o = g_off[gid] + g_bsum[blockIdx.x];
        g_off[gid] = o;
        g_woff[gid] = o;
    }
}

// ---------------- bucket fill: edges sorted by target + norm ----------------

__global__ void k_build(const int* __restrict__ ei,
                        const float* __restrict__ ew, int e) {
    int i = blockIdx.x * blockDim.x + threadIdx.x;
    if (i < e) {
        int r = ei[i];
        int c = ei[e + i];
        float nm = g_deg[r] * ew[i] * g_deg[c];  // dis[row]*ew*dis[col]
        int pos = atomicAdd(&g_woff[c], 1);
        g_csr[pos] = make_int2(r, __float_as_int(nm));
    }
}

// ---------------- encoder MLP: h = relu(x@W1+b1)@W2+b2 ----------------

__global__ void k_encoder(const float* __restrict__ x,
                          const float* __restrict__ w1,
                          const float* __restrict__ b1,
                          const float* __restrict__ w2,
                          const float* __restrict__ b2, int n) {
    __shared__ float4 W2s[DEMB * 16];
    __shared__ float  W1s[2 * DEMB];
    __shared__ float  B1s[DEMB];
    __shared__ float4 B2s[16];
    for (int i = threadIdx.x; i < DEMB * 16; i += blockDim.x)
        W2s[i] = reinterpret_cast<const float4*>(w2)[i];
    for (int i = threadIdx.x; i < 2 * DEMB; i += blockDim.x) W1s[i] = w1[i];
    for (int i = threadIdx.x; i < DEMB; i += blockDim.x) B1s[i] = b1[i];
    for (int i = threadIdx.x; i < 16; i += blockDim.x)
        B2s[i] = reinterpret_cast<const float4*>(b2)[i];
    __syncthreads();

    int nd = blockIdx.x * blockDim.x + threadIdx.x;
    if (nd >= n) return;
    float x0 = x[nd * 2 + 0], x1 = x[nd * 2 + 1];

    unsigned long long a01[16], a23[16];
#pragma unroll
    for (int j = 0; j < 16; j++) {
        float4 b = B2s[j];
        a01[j] = pk(0.0f); a23[j] = pk(0.0f);
        // seed with bias via pack of (b.x,b.y): do it manually
        asm("mov.b64 %0, {%1, %2};" : "=l"(a01[j]) : "f"(b.x), "f"(b.y));
        asm("mov.b64 %0, {%1, %2};" : "=l"(a23[j]) : "f"(b.z), "f"(b.w));
    }

#pragma unroll
    for (int k0 = 0; k0 < 64; k0 += 8) {
        unsigned long long hp[8];
#pragma unroll
        for (int kk = 0; kk < 8; kk++) {
            int k = k0 + kk;
            float h1 = fmaxf(fmaf(x0, W1s[k], fmaf(x1, W1s[DEMB + k], B1s[k])), 0.0f);
            hp[kk] = pk(h1);
        }
#pragma unroll
        for (int kk = 0; kk < 8; kk++) {
#pragma unroll
            for (int j4 = 0; j4 < 16; j4++) {
                ulonglong2 w = *reinterpret_cast<const ulonglong2*>(&W2s[(k0 + kk) * 16 + j4]);
                fma2(a01[j4], hp[kk], w.x);
                fma2(a23[j4], hp[kk], w.y);
            }
        }
    }

    float4* out = reinterpret_cast<float4*>(g_h + nd * DEMB);
#pragma unroll
    for (int j4 = 0; j4 < 16; j4++) {
        float2 lo = upk(a01[j4]);
        float2 hi = upk(a23[j4]);
        out[j4] = make_float4(lo.x, lo.y, hi.x, hi.y);
    }
}

// ---------------- GCN transform (packed f32x2): hw(fp16) = h@W[l]; g_h = selfnorm*hw ----------------

__global__ void k_gemm_gcn(const float* __restrict__ gcn_w, int l, int n) {
    __shared__ float4 Ws[DEMB * 16];
    const float4* Wg = reinterpret_cast<const float4*>(gcn_w + (size_t)l * DEMB * DEMB);
    for (int i = threadIdx.x; i < DEMB * 16; i += blockDim.x) Ws[i] = Wg[i];
    __syncthreads();

    int nd = blockIdx.x * blockDim.x + threadIdx.x;
    if (nd >= n) return;

    const float4* hv = reinterpret_cast<const float4*>(g_h + nd * DEMB);
    unsigned long long a01[16], a23[16];
#pragma unroll
    for (int j = 0; j < 16; j++) { a01[j] = 0ULL; a23[j] = 0ULL; }  // bits of {0.f,0.f}

#pragma unroll
    for (int t = 0; t < 8; t++) {          // 8 tiles of 8 h-values
        float4 ha = hv[t * 2 + 0];
        float4 hb = hv[t * 2 + 1];
        unsigned long long hp[8];
        hp[0] = pk(ha.x); hp[1] = pk(ha.y); hp[2] = pk(ha.z); hp[3] = pk(ha.w);
        hp[4] = pk(hb.x); hp[5] = pk(hb.y); hp[6] = pk(hb.z); hp[7] = pk(hb.w);
#pragma unroll
        for (int kk = 0; kk < 8; kk++) {
            int k = t * 8 + kk;
#pragma unroll
            for (int j4 = 0; j4 < 16; j4++) {
                ulonglong2 w = *reinterpret_cast<const ulonglong2*>(&Ws[k * 16 + j4]);
                fma2(a01[j4], hp[kk], w.x);
                fma2(a23[j4], hp[kk], w.y);
            }
        }
    }

    float sn = g_selfnorm[nd];
    __half2* hwv = g_hwh + (size_t)nd * 32;
    float4* selfv = reinterpret_cast<float4*>(g_h + nd * DEMB);
#pragma unroll
    for (int j4 = 0; j4 < 16; j4++) {
        float2 lo = upk(a01[j4]);
        float2 hi = upk(a23[j4]);
        hwv[j4 * 2 + 0] = __floats2half2_rn(lo.x, lo.y);
        hwv[j4 * 2 + 1] = __floats2half2_rn(hi.x, hi.y);
        selfv[j4] = make_float4(lo.x * sn, lo.y * sn, hi.x * sn, hi.y * sn);
    }
}

// ---------------- pull aggregation: h = relu(self + Σ norm*hw16[src] + b) ----------------
// 16 threads per node; lane owns 4 features. Unrolled x4 for MLP.

__global__ void k_aggregate(const float* __restrict__ gcn_b, int l, int n) {
    int idx = blockIdx.x * blockDim.x + threadIdx.x;
    int v = idx >> 4;
    if (v >= n) return;
    int lane = idx & 15;

    int j   = g_off[v];
    int end = g_off[v + 1];

    float4 acc = reinterpret_cast<const float4*>(g_h)[(size_t)v * 16 + lane];
    float4 b = __ldg(reinterpret_cast<const float4*>(gcn_b + (size_t)l * DEMB) + lane);
    acc.x += b.x; acc.y += b.y; acc.z += b.z; acc.w += b.w;

    const __half2* hw = g_hwh;

    for (; j + 3 < end; j += 4) {
        int2 p0 = __ldg(&g_csr[j + 0]);
        int2 p1 = __ldg(&g_csr[j + 1]);
        int2 p2 = __ldg(&g_csr[j + 2]);
        int2 p3 = __ldg(&g_csr[j + 3]);
        uint2 r0 = *reinterpret_cast<const uint2*>(hw + (size_t)p0.x * 32 + lane * 2);
        uint2 r1 = *reinterpret_cast<const uint2*>(hw + (size_t)p1.x * 32 + lane * 2);
        uint2 r2 = *reinterpret_cast<const uint2*>(hw + (size_t)p2.x * 32 + lane * 2);
        uint2 r3 = *reinterpret_cast<const uint2*>(hw + (size_t)p3.x * 32 + lane * 2);
        float n0 = __int_as_float(p0.y), n1 = __int_as_float(p1.y);
        float n2 = __int_as_float(p2.y), n3 = __int_as_float(p3.y);
        float2 a0 = __half22float2(*reinterpret_cast<__half2*>(&r0.x));
        float2 b0 = __half22float2(*reinterpret_cast<__half2*>(&r0.y));
        float2 a1 = __half22float2(*reinterpret_cast<__half2*>(&r1.x));
        float2 b1h = __half22float2(*reinterpret_cast<__half2*>(&r1.y));
        float2 a2 = __half22float2(*reinterpret_cast<__half2*>(&r2.x));
        float2 b2h = __half22float2(*reinterpret_cast<__half2*>(&r2.y));
        float2 a3 = __half22float2(*reinterpret_cast<__half2*>(&r3.x));
        float2 b3h = __half22float2(*reinterpret_cast<__half2*>(&r3.y));
        acc.x = fmaf(a0.x, n0, acc.x); acc.y = fmaf(a0.y, n0, acc.y);
        acc.z = fmaf(b0.x, n0, acc.z); acc.w = fmaf(b0.y, n0, acc.w);
        acc.x = fmaf(a1.x, n1, acc.x); acc.y = fmaf(a1.y, n1, acc.y);
        acc.z = fmaf(b1h.x, n1, acc.z); acc.w = fmaf(b1h.y, n1, acc.w);
        acc.x = fmaf(a2.x, n2, acc.x); acc.y = fmaf(a2.y, n2, acc.y);
        acc.z = fmaf(b2h.x, n2, acc.z); acc.w = fmaf(b2h.y, n2, acc.w);
        acc.x = fmaf(a3.x, n3, acc.x); acc.y = fmaf(a3.y, n3, acc.y);
        acc.z = fmaf(b3h.x, n3, acc.z); acc.w = fmaf(b3h.y, n3, acc.w);
    }
    for (; j < end; j++) {
        int2 p = __ldg(&g_csr[j]);
        float nm = __int_as_float(p.y);
        uint2 r = *reinterpret_cast<const uint2*>(hw + (size_t)p.x * 32 + lane * 2);
        float2 a0 = __half22float2(*reinterpret_cast<__half2*>(&r.x));
        float2 b0 = __half22float2(*reinterpret_cast<__half2*>(&r.y));
        acc.x = fmaf(a0.x, nm, acc.x); acc.y = fmaf(a0.y, nm, acc.y);
        acc.z = fmaf(b0.x, nm, acc.z); acc.w = fmaf(b0.y, nm, acc.w);
    }

    acc.x = fmaxf(acc.x, 0.0f);
    acc.y = fmaxf(acc.y, 0.0f);
    acc.z = fmaxf(acc.z, 0.0f);
    acc.w = fmaxf(acc.w, 0.0f);
    reinterpret_cast<float4*>(g_h)[(size_t)v * 16 + lane] = acc;
}

// ---------------- decoder + softmax + residual (packed f32x2 first layer) ----------------

__global__ void k_decoder(const float* __restrict__ x,
                          const float* __restrict__ w1,
                          const float* __restrict__ b1,
                          const float* __restrict__ w2,
                          const float* __restrict__ b2,
                          float* __restrict__ out, int n) {
    __shared__ float4 W1s[DEMB * 16];
    __shared__ float4 B1s[16];
    __shared__ float  W2s[DEMB * 2];
    __shared__ float  B2s[2];
    for (int i = threadIdx.x; i < DEMB * 16; i += blockDim.x)
        W1s[i] = reinterpret_cast<const float4*>(w1)[i];
    for (int i = threadIdx.x; i < 16; i += blockDim.x)
        B1s[i] = reinterpret_cast<const float4*>(b1)[i];
    for (int i = threadIdx.x; i < DEMB * 2; i += blockDim.x) W2s[i] = w2[i];
    for (int i = threadIdx.x; i < 2; i += blockDim.x) B2s[i] = b2[i];
    __syncthreads();

    int nd = blockIdx.x * blockDim.x + threadIdx.x;
    if (nd >= n) return;

    const float4* hv = reinterpret_cast<const float4*>(g_h + nd * DEMB);
    unsigned long long a01[16], a23[16];
#pragma unroll
    for (int j = 0; j < 16; j++) {
        float4 b = B1s[j];
        asm("mov.b64 %0, {%1, %2};" : "=l"(a01[j]) : "f"(b.x), "f"(b.y));
        asm("mov.b64 %0, {%1, %2};" : "=l"(a23[j]) : "f"(b.z), "f"(b.w));
    }

#pragma unroll
    for (int t = 0; t < 8; t++) {
        float4 ha = hv[t * 2 + 0];
        float4 hb = hv[t * 2 + 1];
        unsigned long long hp[8];
        hp[0] = pk(ha.x); hp[1] = pk(ha.y); hp[2] = pk(ha.z); hp[3] = pk(ha.w);
        hp[4] = pk(hb.x); hp[5] = pk(hb.y); hp[6] = pk(hb.z); hp[7] = pk(hb.w);
#pragma unroll
        for (int kk = 0; kk < 8; kk++) {
            int k = t * 8 + kk;
#pragma unroll
            for (int j4 = 0; j4 < 16; j4++) {
                ulonglong2 w = *reinterpret_cast<const ulonglong2*>(&W1s[k * 16 + j4]);
                fma2(a01[j4], hp[kk], w.x);
                fma2(a23[j4], hp[kk], w.y);
            }
        }
    }

    float o0 = B2s[0], o1 = B2s[1];
#pragma unroll
    for (int j4 = 0; j4 < 16; j4++) {
        float2 lo = upk(a01[j4]);
        float2 hi = upk(a23[j4]);
        float ax = fmaxf(lo.x, 0.f), ay = fmaxf(lo.y, 0.f);
        float az = fmaxf(hi.x, 0.f), aw = fmaxf(hi.y, 0.f);
        int j = j4 * 4;
        o0 += ax * W2s[(j + 0) * 2 + 0] + ay * W2s[(j + 1) * 2 + 0]
            + az * W2s[(j + 2) * 2 + 0] + aw * W2s[(j + 3) * 2 + 0];
        o1 += ax * W2s[(j + 0) * 2 + 1] + ay * W2s[(j + 1) * 2 + 1]
            + az * W2s[(j + 2) * 2 + 1] + aw * W2s[(j + 3) * 2 + 1];
    }

    float mx = fmaxf(o0, o1);
    float e0 = __expf(o0 - mx), e1 = __expf(o1 - mx);
    float inv = 1.0f / (e0 + e1);
    out[nd * 2 + 0] = e0 * inv + 2.0f * x[nd * 2 + 0];
    out[nd * 2 + 1] = e1 * inv;
}

// ---------------- launch ----------------

extern "C" void kernel_launch(void* const* d_in, const int* in_sizes, int n_in,
                              void* d_out, int out_size) {
    const float* x      = (const float*)d_in[0];
    const int*   ei     = (const int*)d_in[1];
    const float* ew     = (const float*)d_in[2];
    const float* enc_w1 = (const float*)d_in[3];
    const float* enc_b1 = (const float*)d_in[4];
    const float* enc_w2 = (const float*)d_in[5];
    const float* enc_b2 = (const float*)d_in[6];
    const float* gcn_w  = (const float*)d_in[7];
    const float* gcn_b  = (const float*)d_in[8];
    const float* dec_w1 = (const float*)d_in[9];
    const float* dec_b1 = (const float*)d_in[10];
    const float* dec_w2 = (const float*)d_in[11];
    const float* dec_b2 = (const float*)d_in[12];
    float* out = (float*)d_out;

    int n = in_sizes[0] / 2;
    int e = in_sizes[1] / 2;
    int L = in_sizes[7] / (DEMB * DEMB);

    const int BT = 256;
    int nb_n  = (n + BT - 1) / BT;
    int nb_e  = (e + BT - 1) / BT;
    int nb_ag = (n * 16 + BT - 1) / BT;
    int nb_sc = (n + SCAN_B - 1) / SCAN_B;

    // CSR build (once per launch)
    k_init<<<nb_n, BT>>>(n);
    k_hist<<<nb_e, BT>>>(ei, ew, e);
    k_dis<<<nb_n, BT>>>(n);
    k_scan1<<<nb_sc, SCAN_B>>>(n);
    k_scan2<<<1, 128>>>(nb_sc, n, e);
    k_scan3<<<nb_sc, SCAN_B>>>(n);
    k_build<<<nb_e, BT>>>(ei, ew, e);

    // encoder
    k_encoder<<<nb_n, BT>>>(x, enc_w1, enc_b1, enc_w2, enc_b2, n);

    // GCN layers: transform then pull-aggregate (bias+relu fused)
    for (int l = 0; l < L; l++) {
        k_gemm_gcn<<<nb_n, BT>>>(gcn_w, l, n);
        k_aggregate<<<nb_ag, BT>>>(gcn_b, l, n);
    }

    // decoder
    k_decoder<<<nb_n, BT>>>(x, dec_w1, dec_b1, dec_w2, dec_b2, out, n);
}